// round 7
// baseline (speedup 1.0000x reference)
#include <cuda_runtime.h>
#include <math.h>

#define Hd 128
#define Wd 128
#define Bn 4
#define HW (Hd*Wd)

typedef unsigned long long ull;

#define FFMA2(d, a, b) asm("fma.rn.f32x2 %0, %1, %2, %0;" : "+l"(d) : "l"(a), "l"(b))
#define PACKF2(d, lo, hi) asm("mov.b64 %0, {%1, %2};" : "=l"(d) : "f"(lo), "f"(hi))
#define UNPACKF2(lo, hi, d) asm("mov.b64 {%0, %1}, %2;" : "=f"(lo), "=f"(hi) : "l"(d))

// ---------------- scratch (device globals: no allocation allowed) ----------------
__device__ float g_offm[(size_t)Bn*8*27*HW];   // [b*8+g][27][h][w]  offsets(18) + sigmoid mask(9)
__device__ float g_target[(size_t)Bn*64*HW];   // deform output
__device__ float g_mid[(size_t)Bn*64*HW];      // conv1 output

// =====================================================================
// Kernel 1: per-group 3x3 conv producing 18 offset + 9 mask channels.
// grid (32 tiles, 32 bg), block 256. tile 32(w) x 16(h), 2 px/thread.
// Pixel pair packed into one f32x2 lane; weights duplicated in smem.
// 28 channels x 2 dup = 56 floats = 14 ulonglong2 per tap row.
// =====================================================================
__global__ __launch_bounds__(256) void offset_kernel(
    const float* __restrict__ o_in, const float* __restrict__ pw,
    const float* __restrict__ pb,   const float* __restrict__ mw,
    const float* __restrict__ mb)
{
    __shared__ __align__(16) float tile[2][18*36];
    __shared__ __align__(16) float wsm[2][9*56];   // [tap][k*2 dup]

    const int t  = threadIdx.x;
    const int bg = blockIdx.y;
    const int b  = bg >> 3, g = bg & 7;
    const int tx = (blockIdx.x & 3) * 32;
    const int ty = (blockIdx.x >> 2) * 16;
    const int cg = t & 15, row = t >> 4;

    ull accp[28];
#pragma unroll
    for (int k = 0; k < 28; k++) accp[k] = 0ull;

    const float* fbase = o_in + (size_t)(b*64 + g*8) * HW;

    float r_in[3]; float r_w = 0.f;
    auto fetch = [&](int ic) {
        const float* src = fbase + ic * HW;
#pragma unroll
        for (int k = 0; k < 3; k++) {
            int idx = t + k * 256;
            float v = 0.f;
            if (idx < 612) {
                int rr = idx / 34, cc = idx - rr * 34;
                int y = ty - 1 + rr, x = tx - 1 + cc;
                if (y >= 0 && y < Hd && x >= 0 && x < Wd) v = __ldg(&src[y*Wd + x]);
            }
            r_in[k] = v;
        }
        if (t < 243) {
            int kk = t / 9, tap = t - kk * 9;
            r_w = (kk < 18) ? __ldg(&pw[((g*18 + kk)*8 + ic)*9 + tap])
                            : __ldg(&mw[((g*9 + (kk-18))*8 + ic)*9 + tap]);
        }
    };

    fetch(0);
    int buf = 0;
    for (int ic = 0; ic < 8; ic++) {
#pragma unroll
        for (int k = 0; k < 3; k++) {
            int idx = t + k * 256;
            if (idx < 612) { int rr = idx / 34, cc = idx - rr * 34; tile[buf][rr*36 + cc] = r_in[k]; }
        }
        if (t < 243) {
            int kk = t / 9, tap = t - kk * 9;
            wsm[buf][tap*56 + kk*2]     = r_w;
            wsm[buf][tap*56 + kk*2 + 1] = r_w;
        } else if (t < 252) {
            int tap = t - 243;
            wsm[buf][tap*56 + 54] = 0.f;
            wsm[buf][tap*56 + 55] = 0.f;
        }
        __syncthreads();
        if (ic + 1 < 8) fetch(ic + 1);

#pragma unroll
        for (int r = 0; r < 3; r++) {
            int base = (row + r)*36 + cg*2;
            float vv[4] = { tile[buf][base], tile[buf][base+1], tile[buf][base+2], tile[buf][base+3] };
            ull pa[3];
            PACKF2(pa[0], vv[0], vv[1]);
            PACKF2(pa[1], vv[1], vv[2]);
            PACKF2(pa[2], vv[2], vv[3]);
#pragma unroll
            for (int s = 0; s < 3; s++) {
                const ulonglong2* wp = (const ulonglong2*)&wsm[buf][(r*3 + s)*56];
                ull a = pa[s];
                // 14 ulonglong2 words cover all 28 duplicated channels (2 per word)
#pragma unroll
                for (int k2 = 0; k2 < 14; k2++) {
                    ulonglong2 w = wp[k2];
                    FFMA2(accp[k2*2+0], a, w.x);
                    FFMA2(accp[k2*2+1], a, w.y);
                }
            }
        }
        buf ^= 1;
    }

    const int y = ty + row, x = tx + cg*2;
    const size_t outb = (size_t)bg*27*HW + (size_t)y*Wd + x;
#pragma unroll
    for (int k = 0; k < 18; k++) {
        float bv = __ldg(&pb[g*18 + k]);
        float a0, a1; UNPACKF2(a0, a1, accp[k]);
        float2 v = { a0 + bv, a1 + bv };
        *(float2*)&g_offm[outb + (size_t)k*HW] = v;
    }
#pragma unroll
    for (int k = 0; k < 9; k++) {
        float bv = __ldg(&mb[g*9 + k]);
        float a0, a1; UNPACKF2(a0, a1, accp[18 + k]);
        a0 += bv; a1 += bv;
        float2 v = { 1.f/(1.f + expf(-a0)), 1.f/(1.f + expf(-a1)) };
        *(float2*)&g_offm[outb + (size_t)(18 + k)*HW] = v;
    }
}

// =====================================================================
// Kernel 2: deformable bilinear sampling + modulation + cw contraction.
// grid (64 tiles, 32 bg), block 256 = 16x16 pixels, 1 px/thread.
// =====================================================================
__global__ __launch_bounds__(256) void deform_kernel(
    const float* __restrict__ anchor, const float* __restrict__ cw)
{
    __shared__ __align__(16) float cwsm[576];  // [(c*9+n)*8 + oc]
    const int t  = threadIdx.x;
    const int bg = blockIdx.y;
    const int b  = bg >> 3, g = bg & 7;
    const int tx = (blockIdx.x & 7) * 16, ty = (blockIdx.x >> 3) * 16;

    for (int idx = t; idx < 576; idx += 256) {
        int oc = idx & 7; int cn = idx >> 3; int c = cn / 9, n = cn - c*9;
        cwsm[idx] = __ldg(&cw[((g*8 + oc)*8 + c)*9 + n]);
    }
    __syncthreads();

    const int jl = t & 15, il = t >> 4;
    const int i = ty + il, j = tx + jl;
    const float* offb = g_offm + (size_t)bg*27*HW + (size_t)i*Wd + j;
    const float* xb   = anchor + (size_t)(b*64 + g*8) * HW;

    float acc[8];
#pragma unroll
    for (int oc = 0; oc < 8; oc++) acc[oc] = 0.f;

#pragma unroll
    for (int n = 0; n < 9; n++) {
        float px = (float)(i + n/3) + __ldg(&offb[(size_t)n*HW]);
        float py = (float)(j + n%3) + __ldg(&offb[(size_t)(9 + n)*HW]);
        float mm = __ldg(&offb[(size_t)(18 + n)*HW]);
        float fx = floorf(px), fy = floorf(py);
        float x0 = fminf(fmaxf(fx,       0.f), 127.f);
        float x1 = fminf(fmaxf(fx + 1.f, 0.f), 127.f);
        float y0 = fminf(fmaxf(fy,       0.f), 127.f);
        float y1 = fminf(fmaxf(fy + 1.f, 0.f), 127.f);
        float pxc = fminf(fmaxf(px, 0.f), 127.f);
        float pyc = fminf(fmaxf(py, 0.f), 127.f);
        float gx0 = 1.f + (x0 - pxc);
        float gx1 = 1.f - (x1 - pxc);
        float gy0 = 1.f + (y0 - pyc);
        float gy1 = 1.f - (y1 - pyc);
        float glt = gx0*gy0*mm, grb = gx1*gy1*mm, glb = gx0*gy1*mm, grt = gx1*gy0*mm;
        int ix0 = (int)x0 * Wd, ix1 = (int)x1 * Wd;
        int iy0 = (int)y0,       iy1 = (int)y1;
#pragma unroll
        for (int c = 0; c < 8; c++) {
            const float* pl = xb + (size_t)c*HW;
            float v = glt*__ldg(&pl[ix0 + iy0]) + grb*__ldg(&pl[ix1 + iy1])
                    + glb*__ldg(&pl[ix0 + iy1]) + grt*__ldg(&pl[ix1 + iy0]);
            const float4* wp = (const float4*)&cwsm[(c*9 + n)*8];
            float4 w0 = wp[0], w1 = wp[1];
            acc[0] += v*w0.x; acc[1] += v*w0.y; acc[2] += v*w0.z; acc[3] += v*w0.w;
            acc[4] += v*w1.x; acc[5] += v*w1.y; acc[6] += v*w1.z; acc[7] += v*w1.w;
        }
    }

    const size_t ob = (size_t)(b*64 + g*8)*HW + (size_t)i*Wd + j;
#pragma unroll
    for (int oc = 0; oc < 8; oc++) g_target[ob + (size_t)oc*HW] = acc[oc];
}

// =====================================================================
// Kernels 3/4: direct 3x3 conv, 32x32 spatial tile, 16 oc x 4 px per thread.
// Packed fma.rn.f32x2: pixel pairs in 64-bit lanes, weights duplicated in smem
// so one LDS.128 yields two broadcast weight-pairs. Double-buffered.
// =====================================================================
template<int CIN, bool CONCAT, bool RESID>
__device__ __forceinline__ void conv_body(
    const float* __restrict__ inA, const float* __restrict__ inB,
    const float* __restrict__ wgt, const float* __restrict__ bias,
    const float* __restrict__ resid, float* __restrict__ out)
{
    __shared__ __align__(16) float tile[2][34*36];
    __shared__ __align__(16) float wsm[2][9*32];   // [tap][oc*2 dup]

    const int t  = threadIdx.x;
    const int tx = (blockIdx.x & 3) * 32, ty = (blockIdx.x >> 2) * 32;
    const int ocb = blockIdx.y * 16;
    const int b   = blockIdx.z;
    const int cg = t & 7, row = t >> 3;
    const int col0 = cg * 4;

    ull acc2[2][16];   // [px-pair][oc], each lane = 2 pixels
#pragma unroll
    for (int p = 0; p < 2; p++)
#pragma unroll
        for (int o = 0; o < 16; o++) acc2[p][o] = 0ull;

    float r_in[5]; float r_w = 0.f;
    auto fetch = [&](int ic) {
        const float* src;
        if (CONCAT) src = (ic < 64) ? (inA + (size_t)(b*64 + ic)*HW)
                                    : (inB + (size_t)(b*64 + ic - 64)*HW);
        else        src = inA + (size_t)(b*CIN + ic)*HW;
#pragma unroll
        for (int k = 0; k < 5; k++) {
            int idx = t + k * 256;
            float v = 0.f;
            if (idx < 1156) {
                int rr = idx / 34, cc = idx - rr * 34;
                int y = ty - 1 + rr, x = tx - 1 + cc;
                if (y >= 0 && y < Hd && x >= 0 && x < Wd) v = __ldg(&src[y*Wd + x]);
            }
            r_in[k] = v;
        }
        if (t < 144) {
            int o = t / 9, tap = t - o * 9;
            r_w = __ldg(&wgt[((size_t)(ocb + o)*CIN + ic)*9 + tap]);
        }
    };

    fetch(0);
    int buf = 0;
    for (int ic = 0; ic < CIN; ic++) {
#pragma unroll
        for (int k = 0; k < 5; k++) {
            int idx = t + k * 256;
            if (idx < 1156) { int rr = idx / 34, cc = idx - rr * 34; tile[buf][rr*36 + cc] = r_in[k]; }
        }
        if (t < 144) {
            int o = t / 9, tap = t - o * 9;
            wsm[buf][tap*32 + o*2]     = r_w;
            wsm[buf][tap*32 + o*2 + 1] = r_w;
        }
        __syncthreads();
        if (ic + 1 < CIN) fetch(ic + 1);

#pragma unroll
        for (int r = 0; r < 3; r++) {
            const float* trow = &tile[buf][(row + r)*36 + col0];
            float4 v4 = *(const float4*)trow;
            float2 v2 = *(const float2*)(trow + 4);
            float v[6] = { v4.x, v4.y, v4.z, v4.w, v2.x, v2.y };
            // pa[pp][s] = packed pixel pair (2*pp + s, 2*pp + s + 1)
            ull pa[2][3];
            PACKF2(pa[0][0], v[0], v[1]);
            PACKF2(pa[0][1], v[1], v[2]);
            PACKF2(pa[0][2], v[2], v[3]);
            pa[1][0] = pa[0][2];
            PACKF2(pa[1][1], v[3], v[4]);
            PACKF2(pa[1][2], v[4], v[5]);
#pragma unroll
            for (int s = 0; s < 3; s++) {
                const ulonglong2* wp = (const ulonglong2*)&wsm[buf][(r*3 + s)*32];
                ull a0 = pa[0][s], a1 = pa[1][s];
                // 8 ulonglong2 words cover all 16 duplicated oc (2 per word)
#pragma unroll
                for (int o4 = 0; o4 < 8; o4++) {
                    ulonglong2 w = wp[o4];        // {w(2o4) dup, w(2o4+1) dup}
                    FFMA2(acc2[0][o4*2+0], a0, w.x);
                    FFMA2(acc2[0][o4*2+1], a0, w.y);
                    FFMA2(acc2[1][o4*2+0], a1, w.x);
                    FFMA2(acc2[1][o4*2+1], a1, w.y);
                }
            }
        }
        buf ^= 1;
    }

    const int y = ty + row, x = tx + col0;
#pragma unroll
    for (int o = 0; o < 16; o++) {
        float bv = __ldg(&bias[ocb + o]);
        size_t oidx = ((size_t)(b*64 + ocb + o)*Hd + y)*Wd + x;
        float a0, a1, a2, a3;
        UNPACKF2(a0, a1, acc2[0][o]);
        UNPACKF2(a2, a3, acc2[1][o]);
        float4 v = { a0 + bv, a1 + bv, a2 + bv, a3 + bv };
        if (RESID) {
            float4 rr = *(const float4*)&resid[oidx];
            v.x += rr.x; v.y += rr.y; v.z += rr.z; v.w += rr.w;
        }
        *(float4*)&out[oidx] = v;
    }
}

__global__ __launch_bounds__(256, 2) void conv1_kernel(
    const float* __restrict__ anchor, const float* __restrict__ w1,
    const float* __restrict__ b1)
{
    conv_body<128, true, false>(g_target, anchor, w1, b1, nullptr, g_mid);
}

__global__ __launch_bounds__(256, 2) void conv2_kernel(
    const float* __restrict__ w2, const float* __restrict__ b2,
    float* __restrict__ out)
{
    conv_body<64, false, true>(g_mid, nullptr, w2, b2, g_target, out);
}

// =====================================================================
extern "C" void kernel_launch(void* const* d_in, const int* in_sizes, int n_in,
                              void* d_out, int out_size)
{
    const float* o      = (const float*)d_in[0];
    const float* anchor = (const float*)d_in[1];
    const float* pw     = (const float*)d_in[2];
    const float* pb     = (const float*)d_in[3];
    const float* mw     = (const float*)d_in[4];
    const float* mb     = (const float*)d_in[5];
    const float* cw     = (const float*)d_in[6];
    const float* w1     = (const float*)d_in[7];
    const float* b1     = (const float*)d_in[8];
    const float* w2     = (const float*)d_in[9];
    const float* b2     = (const float*)d_in[10];
    float* out = (float*)d_out;

    offset_kernel<<<dim3(32, 32), 256>>>(o, pw, pb, mw, mb);
    deform_kernel<<<dim3(64, 32), 256>>>(anchor, cw);
    conv1_kernel <<<dim3(16, 4, 4), 256>>>(anchor, w1, b1);
    conv2_kernel <<<dim3(16, 4, 4), 256>>>(w2, b2, out);
}